// round 10
// baseline (speedup 1.0000x reference)
#include <cuda_runtime.h>
#include <math.h>

// RepulsionLoss: points [4, 8192, 3] f32 -> scalar f32
// R10: persistent fused kernel (hist -> scan/rowranges -> scatter -> knn)
// with the R9 coherence bugs fixed:
//   - NO __ldg on g_rr / g_sorted (written earlier in the same kernel; the
//     non-coherent read-only path served stale data in R9 -> rel_err 0.82)
//   - grid_barrier does a per-thread __threadfence() before arrival
// 1024 blocks x 288 thr, launch_bounds(288,7): all blocks co-resident
// (7/SM * 148 = 1036 >= 1024), so the generation barrier cannot deadlock.

#define BATCH    4
#define NPTS     8192
#define TOTALPTS (BATCH * NPTS)
#define KNN      8
#define RADIUS   0.07f
#define H2_INV   (1.0f / (0.03f * 0.03f))
#define ALPHA    0.1f

#define GRIDC    14
#define NCELL    (GRIDC * GRIDC * GRIDC)   // 2744
#define CPAD     4096

#define QPB      32
#define NROW     9
#define KBLOCK   (QPB * NROW)              // 288 threads, 9 warps
#define KGRID    (BATCH * NPTS / QPB)      // 1024 blocks (all resident)
#define MSTRIDE  (NROW * KNN + 1)          // 73: conflict-free columns

__device__ int    g_hist[BATCH][CPAD];     // zero at load; re-zeroed each launch
__device__ int    g_off [BATCH][CPAD];
__device__ int    g_cur [BATCH][CPAD];
__device__ int2   g_rr  [BATCH][NCELL];
__device__ float4 g_sorted[BATCH][NPTS];
__device__ float        g_acc;             // restored to 0 by finalize
__device__ unsigned int g_tick;            // ditto
__device__ unsigned int g_bar_cnt;         // barrier arrivals (self-resetting)
__device__ unsigned int g_bar_gen;         // barrier generation (monotonic)

static __device__ __forceinline__ int cell_coord(float v) {
    int c = (int)(v * (float)GRIDC);
    return c > GRIDC - 1 ? GRIDC - 1 : (c < 0 ? 0 : c);
}

// branch-free sorted insert: independent across k, depth 2
static __device__ __forceinline__ void ins8(float best[KNN], float v) {
#pragma unroll
    for (int k = KNN - 1; k > 0; --k)
        best[k] = fminf(best[k], fmaxf(v, best[k - 1]));
    best[0] = fminf(best[0], v);
}

// all-resident software grid barrier. Every thread fences (release) before
// arrival; the fence is also a compiler barrier against load/store motion.
static __device__ __forceinline__ void grid_barrier() {
    __threadfence();
    __syncthreads();
    if (threadIdx.x == 0) {
        volatile unsigned int* genp = (volatile unsigned int*)&g_bar_gen;
        const unsigned int gen = *genp;
        const unsigned int arrived = atomicAdd(&g_bar_cnt, 1u);
        if (arrived == (unsigned)gridDim.x - 1u) {
            g_bar_cnt = 0u;
            __threadfence();
            atomicAdd(&g_bar_gen, 1u);            // release
        } else {
            while (*genp == gen) { __nanosleep(64); }
        }
        __threadfence();                           // acquire
    }
    __syncthreads();
}

__global__ __launch_bounds__(KBLOCK, 7) void repulsion_kernel(
        const float* __restrict__ pts, float* __restrict__ out) {
    __shared__ float s_m[QPB][MSTRIDE];
    __shared__ int   s_wsum[NROW];

    const int tid  = threadIdx.x;
    const int lane = tid & 31;
    const int warp = tid >> 5;
    const int gtid = blockIdx.x * KBLOCK + tid;

    // ---- Phase A: histogram (one point per thread; coords stay in regs) ----
    float px = 0.f, py = 0.f, pz = 0.f;
    int   pb = 0, pc = 0;
    if (gtid < TOTALPTS) {
        pb = gtid >> 13;                       // batch (NPTS = 2^13)
        px = __ldg(pts + 3 * (size_t)gtid + 0);
        py = __ldg(pts + 3 * (size_t)gtid + 1);
        pz = __ldg(pts + 3 * (size_t)gtid + 2);
        pc = (cell_coord(pz) * GRIDC + cell_coord(py)) * GRIDC + cell_coord(px);
        atomicAdd(&g_hist[pb][pc], 1);
    }
    grid_barrier();

    // ---- Phase B: scan + rowranges + hist re-zero (blocks 0..3) -----------
    if (blockIdx.x < BATCH) {
        const int b  = blockIdx.x;
        const int i0 = tid * 16;               // 288*16 = 4608 covers 4096
        int v[16];
        int sum = 0;
#pragma unroll
        for (int r = 0; r < 16; ++r) {
            const int i = i0 + r;
            const int x = (i < CPAD) ? g_hist[b][i] : 0;
            v[r] = x;
            sum += x;
        }
        int inc = sum;
#pragma unroll
        for (int off = 1; off < 32; off <<= 1) {
            const int n = __shfl_up_sync(0xffffffffu, inc, off);
            if (lane >= off) inc += n;
        }
        if (lane == 31) s_wsum[warp] = inc;
        __syncthreads();
        int wbase = 0;
        for (int w = 0; w < warp; ++w) wbase += s_wsum[w];
        int run = wbase + inc - sum;           // exclusive prefix
#pragma unroll
        for (int r = 0; r < 16; ++r) {
            const int i = i0 + r;
            if (i < CPAD) {
                g_off[b][i] = run;
                g_cur[b][i] = run;
                run += v[r];
            }
        }
        __syncthreads();                       // block-wide g_off visibility

        for (int i = tid; i < NCELL; i += KBLOCK) {
            const int x  = i % GRIDC;
            const int rb = i - x;
            const int xs = g_off[b][rb + (x > 0 ? x - 1 : 0)];
            const int xe = g_off[b][rb + (x < GRIDC - 1 ? x + 1 : GRIDC - 1) + 1];
            g_rr[b][i] = make_int2(xs, xe);
        }
        for (int i = tid; i < CPAD; i += KBLOCK)   // fresh hist for next replay
            g_hist[b][i] = 0;
    }
    grid_barrier();

    // ---- Phase C: scatter (same thread, coords from registers) ------------
    if (gtid < TOTALPTS) {
        const int pos = atomicAdd(&g_cur[pb][pc], 1);
        g_sorted[pb][pos] = make_float4(px, py, pz, 0.0f);
    }
    grid_barrier();

    // ---- Phase D: 9-way grid-KNN + loss (plain coherent loads!) -----------
    const int ri     = warp;                   // row index 0..8
    const int qlocal = lane;                   // local query

    const int blocks_per_batch = NPTS / QPB;   // 256
    const int b  = blockIdx.x / blocks_per_batch;
    const int qi = (blockIdx.x % blocks_per_batch) * QPB + qlocal;

    const float4 p = g_sorted[b][qi];          // coherent load (written phase C)
    const float qx = p.x, qy = p.y, qz = p.z;
    const int cx = cell_coord(qx);
    const int cy = cell_coord(qy);
    const int cz = cell_coord(qz);

    float best[KNN];                           // sorted ascending
#pragma unroll
    for (int k = 0; k < KNN; ++k) best[k] = 3.0e38f;

    const int zz = cz - 1 + ri / 3;
    const int yy = cy - 1 + ri % 3;
    if ((unsigned)zz < GRIDC && (unsigned)yy < GRIDC) {
        const int2 r = g_rr[b][(zz * GRIDC + yy) * GRIDC + cx];
#pragma unroll 4
        for (int j = r.x; j < r.y; ++j) {
            const float4 c = g_sorted[b][j];   // coherent load
            const float dx = qx - c.x;
            const float dy = qy - c.y;
            const float dz = qz - c.z;
            const float d2 = fmaf(dx, dx, fmaf(dy, dy, dz * dz));
            ins8(best, d2);
        }
    }

#pragma unroll
    for (int k = 0; k < KNN; ++k) s_m[qlocal][ri * KNN + k] = best[k];
    __syncthreads();

    if (ri == 0) {                             // warp 0 merges + reduces
        float m[KNN];
#pragma unroll
        for (int k = 0; k < KNN; ++k) m[k] = best[k];
#pragma unroll 4
        for (int i = KNN; i < NROW * KNN; ++i)
            ins8(m, s_m[qlocal][i]);

        // unfilled slots (3e38) -> exp underflows to 0 -> contribute nothing
        float s = 0.0f;
#pragma unroll
        for (int k = 0; k < KNN; ++k) {
            const float d2 = m[k];
            const float dn = sqrtf(fmaxf(d2, 1e-12f));
            const float w  = __expf(-d2 * H2_INV);
            s = fmaf(RADIUS - dn, w, s);
        }
#pragma unroll
        for (int off = 16; off > 0; off >>= 1)
            s += __shfl_xor_sync(0xffffffffu, s, off);

        if (qlocal == 0) {
            atomicAdd(&g_acc, s);
            __threadfence();
            const unsigned t = atomicAdd(&g_tick, 1u);
            if (t == KGRID - 1) {              // last block finalizes
                __threadfence();
                const float total = atomicAdd(&g_acc, 0.0f);
                out[0] = ALPHA * total * (1.0f / (float)(BATCH * NPTS * KNN));
                g_acc = 0.0f;                  // restore for graph replay
                __threadfence();
                g_tick = 0u;
            }
        }
    }
}

extern "C" void kernel_launch(void* const* d_in, const int* in_sizes, int n_in,
                              void* d_out, int out_size) {
    const float* pts = (const float*)d_in[0];
    float* out = (float*)d_out;
    repulsion_kernel<<<KGRID, KBLOCK>>>(pts, out);
}

// round 11
// speedup vs baseline: 1.2268x; 1.2268x over previous
#include <cuda_runtime.h>
#include <math.h>

// RepulsionLoss: points [4, 8192, 3] f32 -> scalar f32
// R11: back to the 2-kernel split (fused persistent version lost ~8us to
// per-thread MEMBAR traffic at the software barriers -- the launch boundary
// is a free hardware barrier). New: per-row sphere pruning in the knn.
// Useful region is the ball of radius R_CUT = cell = 1/14 (same error class
// as the 3x3x3 block approximation: excluded terms < 5e-6 each). Per row:
// skip if dy^2+dz^2 > R_CUT^2, else scan x-cells [cell(qx-ax), cell(qx+ax)],
// ax = sqrt(R_CUT^2 - dy^2 - dz^2). Ball/block volume ~0.16 -> ~40% fewer
// candidates and many whole-row skips.

#define BATCH   4
#define NPTS    8192
#define KNN     8
#define RADIUS  0.07f
#define H2_INV  (1.0f / (0.03f * 0.03f))
#define ALPHA   0.1f

#define GRIDC   14
#define CELL    (1.0f / (float)GRIDC)
#define RCUT2   (CELL * CELL)
#define NCELL   (GRIDC * GRIDC * GRIDC)   // 2744
#define CPAD    4096

#define QPB     32                        // queries per knn block
#define NROW    9                         // (zz,yy) rows per query (warp = row)
#define KBLOCK  (QPB * NROW)              // 288 threads, 9 warps
#define KGRID   (BATCH * NPTS / QPB)      // 1024 blocks (one wave at 7/SM)
#define MSTRIDE (NROW * KNN + 1)          // 73: conflict-free columns

#define PPT     8                         // points per thread in build

__device__ int    g_off[BATCH][CPAD];     // cell offsets; off[>=NCELL] = NPTS
__device__ float4 g_sorted[BATCH][NPTS];
__device__ float        g_acc;            // zero-init; restored by finalize
__device__ unsigned int g_tick;           // ditto

static __device__ __forceinline__ int cell_coord(float v) {
    int c = (int)(v * (float)GRIDC);
    return c > GRIDC - 1 ? GRIDC - 1 : (c < 0 ? 0 : c);
}

// branch-free sorted insert: independent across k, depth 2
static __device__ __forceinline__ void ins8(float best[KNN], float v) {
#pragma unroll
    for (int k = KNN - 1; k > 0; --k)
        best[k] = fminf(best[k], fmaxf(v, best[k - 1]));
    best[0] = fminf(best[0], v);
}

// ---- 1: fused build: histogram + scan + scatter (1 block per batch) ----
__global__ __launch_bounds__(1024) void build_kernel(const float* __restrict__ pts) {
    __shared__ int s_cnt[CPAD];           // counts -> offsets -> scatter cursors
    __shared__ int s_wsum[32];

    const int b    = blockIdx.x;
    const int tid  = threadIdx.x;
    const int lane = tid & 31;
    const int warp = tid >> 5;
    const float* __restrict__ base = pts + (size_t)b * NPTS * 3;

    for (int i = tid; i < CPAD; i += 1024) s_cnt[i] = 0;
    __syncthreads();

    float px[PPT], py[PPT], pz[PPT];
    int   pc[PPT];
#pragma unroll
    for (int r = 0; r < PPT; ++r) {
        const int i = r * 1024 + tid;
        px[r] = __ldg(base + 3 * i + 0);
        py[r] = __ldg(base + 3 * i + 1);
        pz[r] = __ldg(base + 3 * i + 2);
        pc[r] = (cell_coord(pz[r]) * GRIDC + cell_coord(py[r])) * GRIDC
                + cell_coord(px[r]);
        atomicAdd(&s_cnt[pc[r]], 1);
    }
    __syncthreads();

    // exclusive scan of 4096 counts, 4 per thread
    const int t4 = tid * 4;
    const int v0 = s_cnt[t4 + 0];
    const int v1 = s_cnt[t4 + 1];
    const int v2 = s_cnt[t4 + 2];
    const int v3 = s_cnt[t4 + 3];
    const int sum = v0 + v1 + v2 + v3;
    int inc = sum;
#pragma unroll
    for (int off = 1; off < 32; off <<= 1) {
        const int n = __shfl_up_sync(0xffffffffu, inc, off);
        if (lane >= off) inc += n;
    }
    if (lane == 31) s_wsum[warp] = inc;
    __syncthreads();
    if (warp == 0) {
        int wv = s_wsum[lane];
#pragma unroll
        for (int off = 1; off < 32; off <<= 1) {
            const int n = __shfl_up_sync(0xffffffffu, wv, off);
            if (lane >= off) wv += n;
        }
        s_wsum[lane] = wv;
    }
    __syncthreads();
    const int base_w = (warp > 0) ? s_wsum[warp - 1] : 0;
    const int ex = base_w + inc - sum;
    // publish offsets (knn reads these), keep cursors in smem for scatter
    g_off[b][t4 + 0] = ex;
    g_off[b][t4 + 1] = ex + v0;
    g_off[b][t4 + 2] = ex + v0 + v1;
    g_off[b][t4 + 3] = ex + v0 + v1 + v2;
    s_cnt[t4 + 0] = ex;
    s_cnt[t4 + 1] = ex + v0;
    s_cnt[t4 + 2] = ex + v0 + v1;
    s_cnt[t4 + 3] = ex + v0 + v1 + v2;
    __syncthreads();

#pragma unroll
    for (int r = 0; r < PPT; ++r) {
        const int pos = atomicAdd(&s_cnt[pc[r]], 1);
        g_sorted[b][pos] = make_float4(px[r], py[r], pz[r], 0.0f);
    }
}

// ---- 2: fused grid-KNN + loss (9 rows/query, sphere-pruned) -------------
__global__ __launch_bounds__(KBLOCK, 7) void knn_kernel(float* __restrict__ out) {
    __shared__ float s_m[QPB][MSTRIDE];

    const int tid    = threadIdx.x;
    const int ri     = tid >> 5;          // row index 0..8 (= warp id)
    const int qlocal = tid & 31;          // lane = local query

    const int blocks_per_batch = NPTS / QPB;           // 256
    const int b  = blockIdx.x / blocks_per_batch;
    const int qi = (blockIdx.x % blocks_per_batch) * QPB + qlocal;

    const float4 p = __ldg(&g_sorted[b][qi]);
    const float qx = p.x, qy = p.y, qz = p.z;
    const int cx = cell_coord(qx);
    const int cy = cell_coord(qy);
    const int cz = cell_coord(qz);

    float best[KNN];                      // sorted ascending
#pragma unroll
    for (int k = 0; k < KNN; ++k) best[k] = 3.0e38f;

    const int zz = cz - 1 + ri / 3;
    const int yy = cy - 1 + ri % 3;
    if ((unsigned)zz < GRIDC && (unsigned)yy < GRIDC) {
        // slab distances from query to this row's y/z cells
        const float dy = fmaxf(0.0f, fmaxf((float)yy * CELL - qy,
                                           qy - (float)(yy + 1) * CELL));
        const float dz = fmaxf(0.0f, fmaxf((float)zz * CELL - qz,
                                           qz - (float)(zz + 1) * CELL));
        const float rem = RCUT2 - dy * dy - dz * dz;
        if (rem > 0.0f) {                 // row intersects the R_CUT ball
            const float ax = sqrtf(rem);
            const int xlo = cell_coord(qx - ax);   // >= cx-1 since ax <= CELL
            const int xhi = cell_coord(qx + ax);   // <= cx+1
            const int rowbase = (zz * GRIDC + yy) * GRIDC;
            const int js = __ldg(&g_off[b][rowbase + xlo]);
            const int je = __ldg(&g_off[b][rowbase + xhi + 1]);
#pragma unroll 4
            for (int j = js; j < je; ++j) {
                const float4 c = __ldg(&g_sorted[b][j]);
                const float ddx = qx - c.x;
                const float ddy = qy - c.y;
                const float ddz = qz - c.z;
                const float d2 = fmaf(ddx, ddx, fmaf(ddy, ddy, ddz * ddz));
                ins8(best, d2);           // unconditional, depth-2
            }
        }
    }

    // publish row partials (stride-73 rows: conflict-free)
#pragma unroll
    for (int k = 0; k < KNN; ++k) s_m[qlocal][ri * KNN + k] = best[k];
    __syncthreads();

    if (ri == 0) {                        // warp 0 merges + reduces
        float m[KNN];
#pragma unroll
        for (int k = 0; k < KNN; ++k) m[k] = best[k];   // own row in regs
#pragma unroll 4
        for (int i = KNN; i < NROW * KNN; ++i)
            ins8(m, s_m[qlocal][i]);

        // unfilled slots (3e38) -> exp underflows to 0 -> contribute nothing
        float s = 0.0f;
#pragma unroll
        for (int k = 0; k < KNN; ++k) {
            const float d2 = m[k];
            const float dn = sqrtf(fmaxf(d2, 1e-12f));
            const float w  = __expf(-d2 * H2_INV);
            s = fmaf(RADIUS - dn, w, s);
        }
#pragma unroll
        for (int off = 16; off > 0; off >>= 1)
            s += __shfl_xor_sync(0xffffffffu, s, off);

        if (qlocal == 0) {
            atomicAdd(&g_acc, s);
            __threadfence();
            const unsigned t = atomicAdd(&g_tick, 1u);
            if (t == KGRID - 1) {              // last block finalizes
                __threadfence();
                const float total = atomicAdd(&g_acc, 0.0f);
                out[0] = ALPHA * total * (1.0f / (float)(BATCH * NPTS * KNN));
                g_acc = 0.0f;                   // restore for graph replay
                __threadfence();
                g_tick = 0u;
            }
        }
    }
}

extern "C" void kernel_launch(void* const* d_in, const int* in_sizes, int n_in,
                              void* d_out, int out_size) {
    const float* pts = (const float*)d_in[0];
    float* out = (float*)d_out;

    build_kernel<<<BATCH, 1024>>>(pts);
    knn_kernel  <<<KGRID, KBLOCK>>>(out);
}

// round 12
// speedup vs baseline: 1.4529x; 1.1842x over previous
#include <cuda_runtime.h>
#include <math.h>

// RepulsionLoss: points [4, 8192, 3] f32 -> scalar f32
// R12: R8 skeleton (2 kernels, g_rr ranges, 9-way row split, branch-free
// ins8) with two work cuts:
//  - GRIDC=16: cell 0.0625. Missed neighbors (8th-NN beyond coverage) each
//    contribute <1e-4 vs per-query sum ~0.095 -> rel_err ~1e-4 << 1e-3.
//    Candidates/query drop 81 -> ~54.
//  - Bitonic pairwise merge of the 9 row top-8s: for ascending a,b:
//    min(a[i], b[7-i]) = the 8 smallest (bitonic), + 12-CE resort.
//    ~3x fewer merge ops than 64 sequential sorted inserts.

#define BATCH   4
#define NPTS    8192
#define KNN     8
#define RADIUS  0.07f
#define H2_INV  (1.0f / (0.03f * 0.03f))
#define ALPHA   0.1f

#define GRIDC   16
#define NCELL   (GRIDC * GRIDC * GRIDC)   // 4096 = 1024*4 (scan-exact)

#define QPB     32                        // queries per knn block
#define NROW    9                         // (zz,yy) rows per query (warp = row)
#define KBLOCK  (QPB * NROW)              // 288 threads, 9 warps
#define KGRID   (BATCH * NPTS / QPB)      // 1024 blocks (one wave at 7/SM)
#define MSTRIDE (NROW * KNN + 1)          // 73: conflict-free columns

#define PPT     8                         // points per thread in build

__device__ int2   g_rr[BATCH][NCELL];     // per-cell 3-wide x-row range
__device__ float4 g_sorted[BATCH][NPTS];
__device__ float        g_acc;            // zero-init; restored by finalize
__device__ unsigned int g_tick;           // ditto

static __device__ __forceinline__ int cell_coord(float v) {
    int c = (int)(v * (float)GRIDC);
    return c > GRIDC - 1 ? GRIDC - 1 : (c < 0 ? 0 : c);
}

// branch-free sorted insert: independent across k, depth 2
static __device__ __forceinline__ void ins8(float best[KNN], float v) {
#pragma unroll
    for (int k = KNN - 1; k > 0; --k)
        best[k] = fminf(best[k], fmaxf(v, best[k - 1]));
    best[0] = fminf(best[0], v);
}

// ---- 1: fused build: histogram + scan + rowranges + scatter ------------
__global__ __launch_bounds__(1024) void build_kernel(const float* __restrict__ pts) {
    __shared__ int s_cnt[NCELL + 1];      // counts -> offsets -> cursors
    __shared__ int s_wsum[32];

    const int b    = blockIdx.x;
    const int tid  = threadIdx.x;
    const int lane = tid & 31;
    const int warp = tid >> 5;
    const float* __restrict__ base = pts + (size_t)b * NPTS * 3;

    for (int i = tid; i < NCELL; i += 1024) s_cnt[i] = 0;
    __syncthreads();

    float px[PPT], py[PPT], pz[PPT];
    int   pc[PPT];
#pragma unroll
    for (int r = 0; r < PPT; ++r) {
        const int i = r * 1024 + tid;
        px[r] = __ldg(base + 3 * i + 0);
        py[r] = __ldg(base + 3 * i + 1);
        pz[r] = __ldg(base + 3 * i + 2);
        pc[r] = (cell_coord(pz[r]) * GRIDC + cell_coord(py[r])) * GRIDC
                + cell_coord(px[r]);
        atomicAdd(&s_cnt[pc[r]], 1);
    }
    __syncthreads();

    // exclusive scan of 4096 counts, 4 per thread
    const int t4 = tid * 4;
    const int v0 = s_cnt[t4 + 0];
    const int v1 = s_cnt[t4 + 1];
    const int v2 = s_cnt[t4 + 2];
    const int v3 = s_cnt[t4 + 3];
    const int sum = v0 + v1 + v2 + v3;
    int inc = sum;
#pragma unroll
    for (int off = 1; off < 32; off <<= 1) {
        const int n = __shfl_up_sync(0xffffffffu, inc, off);
        if (lane >= off) inc += n;
    }
    if (lane == 31) s_wsum[warp] = inc;
    __syncthreads();
    if (warp == 0) {
        int wv = s_wsum[lane];
#pragma unroll
        for (int off = 1; off < 32; off <<= 1) {
            const int n = __shfl_up_sync(0xffffffffu, wv, off);
            if (lane >= off) wv += n;
        }
        s_wsum[lane] = wv;
    }
    __syncthreads();
    const int base_w = (warp > 0) ? s_wsum[warp - 1] : 0;
    const int ex = base_w + inc - sum;
    // each thread rewrites only the 4 cells it read: no cross-thread hazard
    s_cnt[t4 + 0] = ex;
    s_cnt[t4 + 1] = ex + v0;
    s_cnt[t4 + 2] = ex + v0 + v1;
    s_cnt[t4 + 3] = ex + v0 + v1 + v2;
    if (tid == 1023) s_cnt[NCELL] = NPTS;     // sentinel for row-end lookups
    __syncthreads();

    // per-cell 3-wide x-row candidate ranges (offsets globally contiguous)
    for (int i = tid; i < NCELL; i += 1024) {
        const int x  = i & (GRIDC - 1);
        const int rb = i - x;
        const int xs = s_cnt[rb + (x > 0 ? x - 1 : 0)];
        const int xe = s_cnt[rb + (x < GRIDC - 1 ? x + 1 : GRIDC - 1) + 1];
        g_rr[b][i] = make_int2(xs, xe);
    }
    __syncthreads();                          // rr reads done before cursor bumps

#pragma unroll
    for (int r = 0; r < PPT; ++r) {
        const int pos = atomicAdd(&s_cnt[pc[r]], 1);
        g_sorted[b][pos] = make_float4(px[r], py[r], pz[r], 0.0f);
    }
}

// ---- 2: fused grid-KNN + loss (9 rows/query, bitonic merge) -------------
__global__ __launch_bounds__(KBLOCK, 7) void knn_kernel(float* __restrict__ out) {
    __shared__ float s_m[QPB][MSTRIDE];

    const int tid    = threadIdx.x;
    const int ri     = tid >> 5;          // row index 0..8 (= warp id)
    const int qlocal = tid & 31;          // lane = local query

    const int blocks_per_batch = NPTS / QPB;           // 256
    const int b  = blockIdx.x / blocks_per_batch;
    const int qi = (blockIdx.x % blocks_per_batch) * QPB + qlocal;

    const float4 p = __ldg(&g_sorted[b][qi]);
    const float qx = p.x, qy = p.y, qz = p.z;
    const int cx = cell_coord(qx);
    const int cy = cell_coord(qy);
    const int cz = cell_coord(qz);

    float best[KNN];                      // sorted ascending
#pragma unroll
    for (int k = 0; k < KNN; ++k) best[k] = 3.0e38f;

    const int zz = cz - 1 + ri / 3;
    const int yy = cy - 1 + ri % 3;
    if ((unsigned)zz < GRIDC && (unsigned)yy < GRIDC) {
        const int2 r = __ldg(&g_rr[b][(zz * GRIDC + yy) * GRIDC + cx]);
#pragma unroll 4
        for (int j = r.x; j < r.y; ++j) {
            const float4 c = __ldg(&g_sorted[b][j]);
            const float dx = qx - c.x;
            const float dy = qy - c.y;
            const float dz = qz - c.z;
            const float d2 = fmaf(dx, dx, fmaf(dy, dy, dz * dz));
            ins8(best, d2);               // unconditional, depth-2
        }
    }

    // publish row partials (stride-73 rows: conflict-free)
#pragma unroll
    for (int k = 0; k < KNN; ++k) s_m[qlocal][ri * KNN + k] = best[k];
    __syncthreads();

    if (ri == 0) {                        // warp 0 merges + reduces
        float m[KNN];
#pragma unroll
        for (int k = 0; k < KNN; ++k) m[k] = best[k];   // own row (sorted)

        // pairwise bitonic merges of the other 8 sorted row lists
#pragma unroll
        for (int r = 1; r < NROW; ++r) {
            float t[KNN];
#pragma unroll
            for (int i = 0; i < KNN; ++i)      // 8 smallest of union (bitonic)
                t[i] = fminf(m[i], s_m[qlocal][r * KNN + (KNN - 1 - i)]);
            // bitonic resort to ascending: stages 4,2,1
#pragma unroll
            for (int i = 0; i < 4; ++i) {
                const float lo = fminf(t[i], t[i + 4]);
                const float hi = fmaxf(t[i], t[i + 4]);
                t[i] = lo; t[i + 4] = hi;
            }
#pragma unroll
            for (int h = 0; h < 8; h += 4)
#pragma unroll
                for (int i = 0; i < 2; ++i) {
                    const float lo = fminf(t[h + i], t[h + i + 2]);
                    const float hi = fmaxf(t[h + i], t[h + i + 2]);
                    t[h + i] = lo; t[h + i + 2] = hi;
                }
#pragma unroll
            for (int i = 0; i < 8; i += 2) {
                const float lo = fminf(t[i], t[i + 1]);
                const float hi = fmaxf(t[i], t[i + 1]);
                t[i] = lo; t[i + 1] = hi;
            }
#pragma unroll
            for (int i = 0; i < KNN; ++i) m[i] = t[i];
        }

        // unfilled slots (3e38) -> exp underflows to 0 -> contribute nothing
        float s = 0.0f;
#pragma unroll
        for (int k = 0; k < KNN; ++k) {
            const float d2 = m[k];
            const float dn = sqrtf(fmaxf(d2, 1e-12f));
            const float w  = __expf(-d2 * H2_INV);
            s = fmaf(RADIUS - dn, w, s);
        }
#pragma unroll
        for (int off = 16; off > 0; off >>= 1)
            s += __shfl_xor_sync(0xffffffffu, s, off);

        if (qlocal == 0) {
            atomicAdd(&g_acc, s);
            __threadfence();
            const unsigned t = atomicAdd(&g_tick, 1u);
            if (t == KGRID - 1) {              // last block finalizes
                __threadfence();
                const float total = atomicAdd(&g_acc, 0.0f);
                out[0] = ALPHA * total * (1.0f / (float)(BATCH * NPTS * KNN));
                g_acc = 0.0f;                   // restore for graph replay
                __threadfence();
                g_tick = 0u;
            }
        }
    }
}

extern "C" void kernel_launch(void* const* d_in, const int* in_sizes, int n_in,
                              void* d_out, int out_size) {
    const float* pts = (const float*)d_in[0];
    float* out = (float*)d_out;

    build_kernel<<<BATCH, 1024>>>(pts);
    knn_kernel  <<<KGRID, KBLOCK>>>(out);
}

// round 13
// speedup vs baseline: 1.5771x; 1.0855x over previous
#include <cuda_runtime.h>
#include <math.h>

// RepulsionLoss: points [4, 8192, 3] f32 -> scalar f32
// R13: cluster-parallel grid build. Build runs as 32 blocks x 512 thr with
// __cluster_dims__(8): one 8-CTA cluster per batch, hardware cluster.sync
// (~380cy) instead of 4-block serialization (R12 build ran on 4 SMs; its
// random-address scatter alone cost ~4-5us of L1tex store wavefronts).
//   Phase 1: per-block histogram of 1024 pts via global atomics (coords in regs)
//   Phase 2: every rank redundantly scans all 4096 counts in its own smem,
//            writes its 512-cell slice of g_cur (scatter cursors) + g_rr
//   Phase 3: zero own g_hist slice (invariant for next graph replay) + scatter
// knn kernel identical to R12 (12.3us, rel_err 8.3e-8).

#define BATCH   4
#define NPTS    8192
#define KNN     8
#define RADIUS  0.07f
#define H2_INV  (1.0f / (0.03f * 0.03f))
#define ALPHA   0.1f

#define GRIDC   16
#define NCELL   (GRIDC * GRIDC * GRIDC)   // 4096

#define CLU     8                         // CTAs per cluster (= per batch)
#define BT      512                       // build threads per block
#define BPPB    (NPTS / CLU)              // 1024 points per build block
#define BPPT    (BPPB / BT)               // 2 points per build thread
#define SLICE   (NCELL / CLU)             // 512 cells per rank

#define QPB     32                        // queries per knn block
#define NROW    9                         // (zz,yy) rows per query (warp = row)
#define KBLOCK  (QPB * NROW)              // 288 threads, 9 warps
#define KGRID   (BATCH * NPTS / QPB)      // 1024 blocks (one wave at 7/SM)
#define MSTRIDE (NROW * KNN + 1)          // 73: conflict-free columns

__device__ int    g_hist[BATCH][NCELL];   // ZERO invariant at launch entry
__device__ int    g_cur [BATCH][NCELL];   // scatter cursors
__device__ int2   g_rr  [BATCH][NCELL];   // per-cell 3-wide x-row range
__device__ float4 g_sorted[BATCH][NPTS];
__device__ float        g_acc;            // zero-init; restored by finalize
__device__ unsigned int g_tick;           // ditto

static __device__ __forceinline__ int cell_coord(float v) {
    int c = (int)(v * (float)GRIDC);
    return c > GRIDC - 1 ? GRIDC - 1 : (c < 0 ? 0 : c);
}

// branch-free sorted insert: independent across k, depth 2
static __device__ __forceinline__ void ins8(float best[KNN], float v) {
#pragma unroll
    for (int k = KNN - 1; k > 0; --k)
        best[k] = fminf(best[k], fmaxf(v, best[k - 1]));
    best[0] = fminf(best[0], v);
}

static __device__ __forceinline__ void cluster_sync_fenced() {
    __threadfence();   // publish global writes (release)
    asm volatile("barrier.cluster.arrive.aligned;" ::: "memory");
    asm volatile("barrier.cluster.wait.aligned;" ::: "memory");
}

// ---- 1: cluster-parallel build (8 CTAs per batch) -----------------------
__global__ __launch_bounds__(BT) __cluster_dims__(CLU, 1, 1)
void build_kernel(const float* __restrict__ pts) {
    __shared__ int s_off[NCELL + 1];      // full exclusive scan (redundant/rank)
    __shared__ int s_wsum[BT / 32];

    const int b    = blockIdx.x / CLU;
    const int rank = blockIdx.x % CLU;
    const int tid  = threadIdx.x;
    const int lane = tid & 31;
    const int warp = tid >> 5;
    const float* __restrict__ base = pts + (size_t)b * NPTS * 3;

    // ---- Phase 1: histogram (global atomics; coords stay in registers) ----
    float px[BPPT], py[BPPT], pz[BPPT];
    int   pc[BPPT];
#pragma unroll
    for (int r = 0; r < BPPT; ++r) {
        const int i = rank * BPPB + r * BT + tid;
        px[r] = __ldg(base + 3 * i + 0);
        py[r] = __ldg(base + 3 * i + 1);
        pz[r] = __ldg(base + 3 * i + 2);
        pc[r] = (cell_coord(pz[r]) * GRIDC + cell_coord(py[r])) * GRIDC
                + cell_coord(px[r]);
        atomicAdd(&g_hist[b][pc[r]], 1);
    }
    cluster_sync_fenced();

    // ---- Phase 2: redundant full scan in own smem; write own slice --------
    {
        const int t8 = tid * 8;           // 512 threads x 8 cells = 4096
        int v[8];
        int sum = 0;
#pragma unroll
        for (int r = 0; r < 8; ++r) {     // plain coherent loads (L1 was
            v[r] = g_hist[b][t8 + r];     //  invalidated by cluster.sync)
            sum += v[r];
        }
        int inc = sum;
#pragma unroll
        for (int off = 1; off < 32; off <<= 1) {
            const int n = __shfl_up_sync(0xffffffffu, inc, off);
            if (lane >= off) inc += n;
        }
        if (lane == 31) s_wsum[warp] = inc;
        __syncthreads();
        int wbase = 0;
        for (int w = 0; w < warp; ++w) wbase += s_wsum[w];
        int run = wbase + inc - sum;      // exclusive prefix of cell t8
#pragma unroll
        for (int r = 0; r < 8; ++r) {
            s_off[t8 + r] = run;
            run += v[r];
        }
        if (tid == BT - 1) s_off[NCELL] = NPTS;   // sentinel
        __syncthreads();

        // own 512-cell slice: cursors + 3-wide x-row ranges
        const int i = rank * SLICE + tid;          // SLICE == BT
        g_cur[b][i] = s_off[i];
        const int x  = i & (GRIDC - 1);
        const int rb = i - x;
        const int xs = s_off[rb + (x > 0 ? x - 1 : 0)];
        const int xe = s_off[rb + (x < GRIDC - 1 ? x + 1 : GRIDC - 1) + 1];
        g_rr[b][i] = make_int2(xs, xe);
    }
    cluster_sync_fenced();

    // ---- Phase 3: restore g_hist zero-invariant + scatter ------------------
    g_hist[b][rank * SLICE + tid] = 0;
#pragma unroll
    for (int r = 0; r < BPPT; ++r) {
        const int pos = atomicAdd(&g_cur[b][pc[r]], 1);
        g_sorted[b][pos] = make_float4(px[r], py[r], pz[r], 0.0f);
    }
}

// ---- 2: fused grid-KNN + loss (identical to R12) ------------------------
__global__ __launch_bounds__(KBLOCK, 7) void knn_kernel(float* __restrict__ out) {
    __shared__ float s_m[QPB][MSTRIDE];

    const int tid    = threadIdx.x;
    const int ri     = tid >> 5;          // row index 0..8 (= warp id)
    const int qlocal = tid & 31;          // lane = local query

    const int blocks_per_batch = NPTS / QPB;           // 256
    const int b  = blockIdx.x / blocks_per_batch;
    const int qi = (blockIdx.x % blocks_per_batch) * QPB + qlocal;

    const float4 p = __ldg(&g_sorted[b][qi]);
    const float qx = p.x, qy = p.y, qz = p.z;
    const int cx = cell_coord(qx);
    const int cy = cell_coord(qy);
    const int cz = cell_coord(qz);

    float best[KNN];                      // sorted ascending
#pragma unroll
    for (int k = 0; k < KNN; ++k) best[k] = 3.0e38f;

    const int zz = cz - 1 + ri / 3;
    const int yy = cy - 1 + ri % 3;
    if ((unsigned)zz < GRIDC && (unsigned)yy < GRIDC) {
        const int2 r = __ldg(&g_rr[b][(zz * GRIDC + yy) * GRIDC + cx]);
#pragma unroll 4
        for (int j = r.x; j < r.y; ++j) {
            const float4 c = __ldg(&g_sorted[b][j]);
            const float dx = qx - c.x;
            const float dy = qy - c.y;
            const float dz = qz - c.z;
            const float d2 = fmaf(dx, dx, fmaf(dy, dy, dz * dz));
            ins8(best, d2);               // unconditional, depth-2
        }
    }

    // publish row partials (stride-73 rows: conflict-free)
#pragma unroll
    for (int k = 0; k < KNN; ++k) s_m[qlocal][ri * KNN + k] = best[k];
    __syncthreads();

    if (ri == 0) {                        // warp 0 merges + reduces
        float m[KNN];
#pragma unroll
        for (int k = 0; k < KNN; ++k) m[k] = best[k];   // own row (sorted)

        // pairwise bitonic merges of the other 8 sorted row lists
#pragma unroll
        for (int r = 1; r < NROW; ++r) {
            float t[KNN];
#pragma unroll
            for (int i = 0; i < KNN; ++i)      // 8 smallest of union (bitonic)
                t[i] = fminf(m[i], s_m[qlocal][r * KNN + (KNN - 1 - i)]);
            // bitonic resort to ascending: stages 4,2,1
#pragma unroll
            for (int i = 0; i < 4; ++i) {
                const float lo = fminf(t[i], t[i + 4]);
                const float hi = fmaxf(t[i], t[i + 4]);
                t[i] = lo; t[i + 4] = hi;
            }
#pragma unroll
            for (int h = 0; h < 8; h += 4)
#pragma unroll
                for (int i = 0; i < 2; ++i) {
                    const float lo = fminf(t[h + i], t[h + i + 2]);
                    const float hi = fmaxf(t[h + i], t[h + i + 2]);
                    t[h + i] = lo; t[h + i + 2] = hi;
                }
#pragma unroll
            for (int i = 0; i < 8; i += 2) {
                const float lo = fminf(t[i], t[i + 1]);
                const float hi = fmaxf(t[i], t[i + 1]);
                t[i] = lo; t[i + 1] = hi;
            }
#pragma unroll
            for (int i = 0; i < KNN; ++i) m[i] = t[i];
        }

        // unfilled slots (3e38) -> exp underflows to 0 -> contribute nothing
        float s = 0.0f;
#pragma unroll
        for (int k = 0; k < KNN; ++k) {
            const float d2 = m[k];
            const float dn = sqrtf(fmaxf(d2, 1e-12f));
            const float w  = __expf(-d2 * H2_INV);
            s = fmaf(RADIUS - dn, w, s);
        }
#pragma unroll
        for (int off = 16; off > 0; off >>= 1)
            s += __shfl_xor_sync(0xffffffffu, s, off);

        if (qlocal == 0) {
            atomicAdd(&g_acc, s);
            __threadfence();
            const unsigned t = atomicAdd(&g_tick, 1u);
            if (t == KGRID - 1) {              // last block finalizes
                __threadfence();
                const float total = atomicAdd(&g_acc, 0.0f);
                out[0] = ALPHA * total * (1.0f / (float)(BATCH * NPTS * KNN));
                g_acc = 0.0f;                   // restore for graph replay
                __threadfence();
                g_tick = 0u;
            }
        }
    }
}

extern "C" void kernel_launch(void* const* d_in, const int* in_sizes, int n_in,
                              void* d_out, int out_size) {
    const float* pts = (const float*)d_in[0];
    float* out = (float*)d_out;

    build_kernel<<<BATCH * CLU, BT>>>(pts);
    knn_kernel  <<<KGRID, KBLOCK>>>(out);
}